// round 1
// baseline (speedup 1.0000x reference)
#include <cuda_runtime.h>

#define NEXP   8
#define BTOK   4096
#define DIN    1024
#define DHID   4096
#define DOUT   1024

// Scratch (64 MB) + bucketing state. __device__ globals (no allocation in kernel_launch).
__device__ float g_h[(size_t)BTOK * DHID];
__device__ int   g_counts[NEXP];
__device__ int   g_offsets[NEXP];
__device__ int   g_rank[BTOK];
__device__ int   g_order[BTOK];
__device__ int   g_is32;

// ---------------------------------------------------------------------------
// Routing / bucketing
// ---------------------------------------------------------------------------
__global__ void reset_kernel() {
    if (threadIdx.x < NEXP) g_counts[threadIdx.x] = 0;
    if (threadIdx.x == 0)   g_is32 = 0;
}

// route may be int32 (B ints) or int64 (B longs). Reading the first BTOK
// int32 words is safe under either layout. Values are 0..7, so if route is
// int64 every odd int32 word is the zero hi-half. If route is int32, the odd
// words are route[1],route[3],... — all-zero has probability 8^-2048.
__global__ void detect_kernel(const int* __restrict__ r32) {
    int i = blockIdx.x * blockDim.x + threadIdx.x;   // 0..2047
    int idx = 2 * i + 1;
    if (idx < BTOK && r32[idx] != 0) atomicOr(&g_is32, 1);
}

__device__ __forceinline__ int load_route(const void* route, int b) {
    if (g_is32) return ((const int*)route)[b];
    return (int)((const long long*)route)[b];
}

__global__ void count_kernel(const void* __restrict__ route) {
    int b = blockIdx.x * blockDim.x + threadIdx.x;
    if (b < BTOK) {
        int m = load_route(route, b);
        g_rank[b] = atomicAdd(&g_counts[m], 1);
    }
}

__global__ void scan_kernel() {
    if (threadIdx.x == 0) {
        int s = 0;
        for (int m = 0; m < NEXP; m++) { g_offsets[m] = s; s += g_counts[m]; }
    }
}

__global__ void scatter_kernel(const void* __restrict__ route) {
    int b = blockIdx.x * blockDim.x + threadIdx.x;
    if (b < BTOK) {
        int m = load_route(route, b);
        g_order[g_offsets[m] + g_rank[b]] = b;
    }
}

// ---------------------------------------------------------------------------
// Grouped GEMM: C[rows_of_expert_m] = epi(A @ W[m] + bias[m])
//   LAYER1: A = x gathered via g_order, C = g_h (grouped contiguous), GELU epi
//  !LAYER1: A = g_h (grouped contiguous), C = out scattered via g_order
// Tile 64x64, BK=16, 256 threads, 4x4 microtile per thread.
// ---------------------------------------------------------------------------
__device__ __forceinline__ float gelu_tanh(float x) {
    // jax.nn.gelu approximate=True
    float x3 = x * x * x;
    return 0.5f * x * (1.0f + tanhf(0.7978845608028654f * (x + 0.044715f * x3)));
}

template <int K, int N, bool LAYER1>
__global__ __launch_bounds__(256)
void grouped_gemm_kernel(const float* __restrict__ Ax,
                         const float* __restrict__ W,
                         const float* __restrict__ bias,
                         float* __restrict__ Cout)
{
    const int m    = blockIdx.z;
    const int cnt  = g_counts[m];
    const int row0 = blockIdx.y * 64;
    if (row0 >= cnt) return;
    const int goff = g_offsets[m];
    const int n0   = blockIdx.x * 64;
    const int tid  = threadIdx.x;

    __shared__ float As[16][64];
    __shared__ float Bs[16][64];

    // A staging: 4 threads per row, each loads one float4 along K
    const int a_row = tid >> 2;          // 0..63
    const int a_k   = (tid & 3) * 4;     // 0,4,8,12
    // B staging: 16 threads per k-row, each loads one float4 along N
    const int b_k   = tid >> 4;          // 0..15
    const int b_n   = (tid & 15) * 4;    // 0..60

    const int  grow    = row0 + a_row;
    const bool a_valid = (grow < cnt);

    const float* Arow;
    if (LAYER1) {
        int tok = a_valid ? g_order[goff + grow] : 0;
        Arow = Ax + (size_t)tok * K;
    } else {
        int gr = a_valid ? (goff + grow) : goff;   // clamp (cnt>=1 here)
        Arow = g_h + (size_t)gr * K;
    }

    const float* Wbase = W + (size_t)m * K * N + n0;

    float acc[4][4] = {};
    const int ty4 = (tid >> 4) * 4;      // compute rows ty4..ty4+3
    const int tx4 = (tid & 15) * 4;      // compute cols tx4..tx4+3

    for (int k0 = 0; k0 < K; k0 += 16) {
        float4 av = a_valid ? *reinterpret_cast<const float4*>(Arow + k0 + a_k)
                            : make_float4(0.f, 0.f, 0.f, 0.f);
        As[a_k + 0][a_row] = av.x;
        As[a_k + 1][a_row] = av.y;
        As[a_k + 2][a_row] = av.z;
        As[a_k + 3][a_row] = av.w;

        float4 bv = *reinterpret_cast<const float4*>(Wbase + (size_t)(k0 + b_k) * N + b_n);
        *reinterpret_cast<float4*>(&Bs[b_k][b_n]) = bv;

        __syncthreads();

        #pragma unroll
        for (int k = 0; k < 16; k++) {
            float4 a = *reinterpret_cast<const float4*>(&As[k][ty4]);
            float4 b = *reinterpret_cast<const float4*>(&Bs[k][tx4]);
            acc[0][0] += a.x * b.x; acc[0][1] += a.x * b.y; acc[0][2] += a.x * b.z; acc[0][3] += a.x * b.w;
            acc[1][0] += a.y * b.x; acc[1][1] += a.y * b.y; acc[1][2] += a.y * b.z; acc[1][3] += a.y * b.w;
            acc[2][0] += a.z * b.x; acc[2][1] += a.z * b.y; acc[2][2] += a.z * b.z; acc[2][3] += a.z * b.w;
            acc[3][0] += a.w * b.x; acc[3][1] += a.w * b.y; acc[3][2] += a.w * b.z; acc[3][3] += a.w * b.w;
        }
        __syncthreads();
    }

    // Epilogue
    const float* brow = bias + (size_t)m * N + n0 + tx4;
    float bv0 = brow[0], bv1 = brow[1], bv2 = brow[2], bv3 = brow[3];

    #pragma unroll
    for (int i = 0; i < 4; i++) {
        int r = row0 + ty4 + i;
        if (r >= cnt) break;
        float v0 = acc[i][0] + bv0;
        float v1 = acc[i][1] + bv1;
        float v2 = acc[i][2] + bv2;
        float v3 = acc[i][3] + bv3;
        if (LAYER1) {
            v0 = gelu_tanh(v0); v1 = gelu_tanh(v1);
            v2 = gelu_tanh(v2); v3 = gelu_tanh(v3);
            float* Crow = g_h + (size_t)(goff + r) * N + n0 + tx4;
            Crow[0] = v0; Crow[1] = v1; Crow[2] = v2; Crow[3] = v3;
        } else {
            int tok = g_order[goff + r];
            float* Crow = Cout + (size_t)tok * N + n0 + tx4;
            Crow[0] = v0; Crow[1] = v1; Crow[2] = v2; Crow[3] = v3;
        }
    }
}

// ---------------------------------------------------------------------------
extern "C" void kernel_launch(void* const* d_in, const int* in_sizes, int n_in,
                              void* d_out, int out_size)
{
    const float* x     = (const float*)d_in[0];
    const void*  route = d_in[1];
    const float* W1    = (const float*)d_in[2];
    const float* b1    = (const float*)d_in[3];
    const float* W2    = (const float*)d_in[4];
    const float* b2    = (const float*)d_in[5];
    float*       out   = (float*)d_out;

    reset_kernel<<<1, 32>>>();
    detect_kernel<<<(BTOK / 2 + 255) / 256, 256>>>((const int*)route);
    count_kernel<<<(BTOK + 255) / 256, 256>>>(route);
    scan_kernel<<<1, 32>>>();
    scatter_kernel<<<(BTOK + 255) / 256, 256>>>(route);

    // Layer 1: h = gelu(x @ W1[m] + b1[m]), grouped by expert into g_h
    {
        dim3 grid(DHID / 64, BTOK / 64, NEXP);
        grouped_gemm_kernel<DIN, DHID, true><<<grid, 256>>>(x, W1, b1, nullptr);
    }
    // Layer 2: out[tok] = h @ W2[m] + b2[m], scattered back to token order
    {
        dim3 grid(DOUT / 64, BTOK / 64, NEXP);
        grouped_gemm_kernel<DHID, DOUT, false><<<grid, 256>>>(nullptr, W2, b2, out);
    }
}

// round 3
// speedup vs baseline: 2.7479x; 2.7479x over previous
#include <cuda_runtime.h>
#include <cuda_bf16.h>
#include <stdint.h>
#include <math.h>

#define NEXP 8
#define BTOK 4096
#define DIN  1024
#define DHID 4096
#define DOUT 1024

// Scratch + bucketing state (device globals; no allocations in kernel_launch)
__device__ float g_h[(size_t)BTOK * DHID];
__device__ int   g_counts[NEXP];
__device__ int   g_offsets[NEXP];
__device__ int   g_order[BTOK];

// ---------------------------------------------------------------------------
// Helpers
// ---------------------------------------------------------------------------
__device__ __forceinline__ uint32_t smem_u32(const void* p) {
    uint32_t a;
    asm("{ .reg .u64 t; cvta.to.shared.u64 t, %1; cvt.u32.u64 %0, t; }"
        : "=r"(a) : "l"(p));
    return a;
}

__device__ __forceinline__ void ldm_x4(uint32_t* r, uint32_t addr) {
    asm volatile("ldmatrix.sync.aligned.m8n8.x4.shared.b16 {%0,%1,%2,%3}, [%4];"
                 : "=r"(r[0]), "=r"(r[1]), "=r"(r[2]), "=r"(r[3]) : "r"(addr));
}
__device__ __forceinline__ void ldm_x4_t(uint32_t* r, uint32_t addr) {
    asm volatile("ldmatrix.sync.aligned.m8n8.x4.trans.shared.b16 {%0,%1,%2,%3}, [%4];"
                 : "=r"(r[0]), "=r"(r[1]), "=r"(r[2]), "=r"(r[3]) : "r"(addr));
}

__device__ __forceinline__ void mma_bf16(float* d, const uint32_t* a,
                                         uint32_t b0, uint32_t b1) {
    asm volatile(
        "mma.sync.aligned.m16n8k16.row.col.f32.bf16.bf16.f32 "
        "{%0,%1,%2,%3}, {%4,%5,%6,%7}, {%8,%9}, {%0,%1,%2,%3};"
        : "+f"(d[0]), "+f"(d[1]), "+f"(d[2]), "+f"(d[3])
        : "r"(a[0]), "r"(a[1]), "r"(a[2]), "r"(a[3]), "r"(b0), "r"(b1));
}

__device__ __forceinline__ void sts64(uint32_t addr, uint2 v) {
    asm volatile("st.shared.v2.b32 [%0], {%1, %2};"
                 :: "r"(addr), "r"(v.x), "r"(v.y) : "memory");
}

__device__ __forceinline__ float gelu_tanh(float x) {
    float x3 = x * x * x;
    return 0.5f * x * (1.0f + tanhf(0.7978845608028654f * (x + 0.044715f * x3)));
}

__device__ __forceinline__ uint32_t pack_bf2(__nv_bfloat16 a, __nv_bfloat16 b) {
    __nv_bfloat162 t(a, b);
    return *reinterpret_cast<uint32_t*>(&t);
}

__device__ __forceinline__ void split4(float4 v, uint2& hi, uint2& lo) {
    __nv_bfloat16 h0 = __float2bfloat16(v.x);
    __nv_bfloat16 h1 = __float2bfloat16(v.y);
    __nv_bfloat16 h2 = __float2bfloat16(v.z);
    __nv_bfloat16 h3 = __float2bfloat16(v.w);
    __nv_bfloat16 l0 = __float2bfloat16(v.x - __bfloat162float(h0));
    __nv_bfloat16 l1 = __float2bfloat16(v.y - __bfloat162float(h1));
    __nv_bfloat16 l2 = __float2bfloat16(v.z - __bfloat162float(h2));
    __nv_bfloat16 l3 = __float2bfloat16(v.w - __bfloat162float(h3));
    hi.x = pack_bf2(h0, h1); hi.y = pack_bf2(h2, h3);
    lo.x = pack_bf2(l0, l1); lo.y = pack_bf2(l2, l3);
}

// ---------------------------------------------------------------------------
// Single-block routing: detect route dtype, count, scan, scatter.
// ---------------------------------------------------------------------------
__global__ __launch_bounds__(1024)
void route_kernel(const int* __restrict__ r32) {
    __shared__ int s32, scnt[NEXP], soff[NEXP];
    int tid = threadIdx.x;
    if (tid == 0) s32 = 0;
    if (tid < NEXP) scnt[tid] = 0;
    __syncthreads();

    // int64 route: every odd int32 word of the first 4096 is a zero hi-half.
    int f = 0;
    for (int i = tid * 2 + 1; i < BTOK; i += 2048) f |= r32[i];
    if (f) atomicOr(&s32, 1);
    __syncthreads();
    bool is32 = (s32 != 0);

    int mym[4], myrank[4];
    #pragma unroll
    for (int j = 0; j < 4; j++) {
        int b = tid + j * 1024;
        int m = is32 ? r32[b] : (int)((const long long*)r32)[b];
        mym[j] = m;
        myrank[j] = atomicAdd(&scnt[m], 1);
    }
    __syncthreads();
    if (tid == 0) {
        int s = 0;
        for (int m = 0; m < NEXP; m++) {
            soff[m] = s; g_offsets[m] = s; g_counts[m] = scnt[m]; s += scnt[m];
        }
    }
    __syncthreads();
    #pragma unroll
    for (int j = 0; j < 4; j++)
        g_order[soff[mym[j]] + myrank[j]] = tid + j * 1024;
}

// ---------------------------------------------------------------------------
// Grouped GEMM, mma.sync m16n8k16 bf16, split hi/lo (3 passes), fp32 acc.
// CTA tile 128x128, K-chunk 32, 8 warps (4 m x 2 n), warp tile 32x64.
// Double-buffered SMEM, padded strides (conflict-free ldmatrix).
// ---------------------------------------------------------------------------
static constexpr int ASTR_B = 80;    // A row stride, bytes (40 bf16)
static constexpr int BSTR_B = 272;   // B row stride, bytes (136 bf16)
static constexpr int A_TILE = 128 * ASTR_B;            // 10240
static constexpr int B_TILE = 32 * BSTR_B;             // 8704
static constexpr int OFF_AHI = 0;
static constexpr int OFF_ALO = A_TILE;                 // 10240
static constexpr int OFF_BHI = 2 * A_TILE;             // 20480
static constexpr int OFF_BLO = 2 * A_TILE + B_TILE;    // 29184
static constexpr int STAGE   = 2 * A_TILE + 2 * B_TILE;// 37888
static constexpr int SMEM_DYN = 2 * STAGE;             // 75776

template <int K, int NTOT, bool LAYER1>
__global__ __launch_bounds__(256)
void moe_gemm(const float* __restrict__ Ax, const float* __restrict__ W,
              const float* __restrict__ bias, float* __restrict__ Cout)
{
    const int m    = blockIdx.z;
    const int cnt  = g_counts[m];
    const int row0 = blockIdx.y * 128;
    if (row0 >= cnt) return;
    const int goff = g_offsets[m];
    const int n0   = blockIdx.x * 128;
    const int tid  = threadIdx.x;
    const int wid  = tid >> 5;
    const int lane = tid & 31;
    const int wm   = wid & 3;    // warp row 0..3  (32 rows each)
    const int wn   = wid >> 2;   // warp col 0..1  (64 cols each)

    extern __shared__ char smem_raw[];
    const uint32_t sbase = smem_u32(smem_raw);

    // ---- Per-thread global load mapping ----
    // A: 128 rows x 32 floats = 1024 float4; thread handles 4.
    const float* aptr[4];
    int akoff[4];
    #pragma unroll
    for (int j = 0; j < 4; j++) {
        int idx  = tid + j * 256;
        int row  = idx >> 3;             // 0..127
        akoff[j] = (idx & 7) * 4;        // float offset in chunk (0..28)
        int grow = row0 + row;
        int gr   = (grow < cnt) ? (goff + grow) : goff;   // clamp
        if (LAYER1) aptr[j] = Ax + (size_t)g_order[gr] * K;
        else        aptr[j] = g_h + (size_t)gr * K;
    }
    // B: 32 k-rows x 128 floats = 1024 float4; thread handles 4.
    const float* Wb = W + (size_t)m * K * NTOT + n0;
    int bkrow[4], bnoff[4];
    #pragma unroll
    for (int j = 0; j < 4; j++) {
        int idx  = tid + j * 256;
        bkrow[j] = idx >> 5;             // 0..31
        bnoff[j] = (idx & 31) * 4;       // 0..124
    }

    // SMEM store addresses (stage-relative, bytes)
    uint32_t a_sts[4], b_sts[4];
    #pragma unroll
    for (int j = 0; j < 4; j++) {
        int idx = tid + j * 256;
        a_sts[j] = (uint32_t)((idx >> 3) * ASTR_B + (idx & 7) * 8);
        b_sts[j] = (uint32_t)((idx >> 5) * BSTR_B + (idx & 31) * 8);
    }

    // ldmatrix base addresses (stage-relative)
    // A frag (m16k16): row = wm*32 + mt*16 + (lane&15); koff = (lane>>4)*8 elems
    const uint32_t a_ldm = (uint32_t)((wm * 32 + (lane & 15)) * ASTR_B + (lane >> 4) * 16);
    // B frag (k16n16, trans): krow = kstep*16 + (lane&15); col = wn*64 + ng*16 + (lane>>4)*8
    const uint32_t b_ldm = (uint32_t)((lane & 15) * BSTR_B + (wn * 64 + (lane >> 4) * 8) * 2);

    float acc[2][8][4] = {};

    const int NC = K / 32;
    float4 av[4], bv[4];

    // Prefetch chunk 0
    #pragma unroll
    for (int j = 0; j < 4; j++)
        av[j] = *reinterpret_cast<const float4*>(aptr[j] + akoff[j]);
    #pragma unroll
    for (int j = 0; j < 4; j++)
        bv[j] = *reinterpret_cast<const float4*>(Wb + (size_t)bkrow[j] * NTOT + bnoff[j]);

    // Store chunk 0 into stage 0
    {
        const uint32_t st = sbase;
        #pragma unroll
        for (int j = 0; j < 4; j++) {
            uint2 hi, lo; split4(av[j], hi, lo);
            sts64(st + OFF_AHI + a_sts[j], hi);
            sts64(st + OFF_ALO + a_sts[j], lo);
        }
        #pragma unroll
        for (int j = 0; j < 4; j++) {
            uint2 hi, lo; split4(bv[j], hi, lo);
            sts64(st + OFF_BHI + b_sts[j], hi);
            sts64(st + OFF_BLO + b_sts[j], lo);
        }
    }
    __syncthreads();

    for (int c = 0; c < NC; c++) {
        // Prefetch next chunk into registers (overlaps with MMA below)
        if (c + 1 < NC) {
            const int k0 = (c + 1) * 32;
            #pragma unroll
            for (int j = 0; j < 4; j++)
                av[j] = *reinterpret_cast<const float4*>(aptr[j] + k0 + akoff[j]);
            #pragma unroll
            for (int j = 0; j < 4; j++)
                bv[j] = *reinterpret_cast<const float4*>(
                            Wb + (size_t)(k0 + bkrow[j]) * NTOT + bnoff[j]);
        }

        // MMA on current stage
        const uint32_t st = sbase + (c & 1) * STAGE;
        #pragma unroll
        for (int ks = 0; ks < 2; ks++) {
            uint32_t ahi[2][4], alo[2][4];
            #pragma unroll
            for (int mt = 0; mt < 2; mt++) {
                uint32_t aoff = a_ldm + mt * 16 * ASTR_B + ks * 32;
                ldm_x4(ahi[mt], st + OFF_AHI + aoff);
                ldm_x4(alo[mt], st + OFF_ALO + aoff);
            }
            #pragma unroll
            for (int ng = 0; ng < 4; ng++) {
                uint32_t bhi[4], blo[4];
                uint32_t boff = b_ldm + ks * 16 * BSTR_B + ng * 32;
                ldm_x4_t(bhi, st + OFF_BHI + boff);
                ldm_x4_t(blo, st + OFF_BLO + boff);
                #pragma unroll
                for (int mt = 0; mt < 2; mt++) {
                    float* d0 = acc[mt][ng * 2 + 0];
                    float* d1 = acc[mt][ng * 2 + 1];
                    mma_bf16(d0, ahi[mt], bhi[0], bhi[1]);
                    mma_bf16(d1, ahi[mt], bhi[2], bhi[3]);
                    mma_bf16(d0, ahi[mt], blo[0], blo[1]);
                    mma_bf16(d1, ahi[mt], blo[2], blo[3]);
                    mma_bf16(d0, alo[mt], bhi[0], bhi[1]);
                    mma_bf16(d1, alo[mt], bhi[2], bhi[3]);
                }
            }
        }

        // Store prefetched chunk into the other stage
        if (c + 1 < NC) {
            const uint32_t st2 = sbase + ((c + 1) & 1) * STAGE;
            #pragma unroll
            for (int j = 0; j < 4; j++) {
                uint2 hi, lo; split4(av[j], hi, lo);
                sts64(st2 + OFF_AHI + a_sts[j], hi);
                sts64(st2 + OFF_ALO + a_sts[j], lo);
            }
            #pragma unroll
            for (int j = 0; j < 4; j++) {
                uint2 hi, lo; split4(bv[j], hi, lo);
                sts64(st2 + OFF_BHI + b_sts[j], hi);
                sts64(st2 + OFF_BLO + b_sts[j], lo);
            }
        }
        __syncthreads();
    }

    // ---- Epilogue ----
    // D frag m16n8: d0,d1 -> row lane>>2, cols (lane&3)*2+{0,1}; d2,d3 -> row+8
    const float* bp = bias + (size_t)m * NTOT + n0;
    #pragma unroll
    for (int mt = 0; mt < 2; mt++) {
        #pragma unroll
        for (int half = 0; half < 2; half++) {
            int rloc = wm * 32 + mt * 16 + (lane >> 2) + half * 8;
            int r    = row0 + rloc;
            if (r < cnt) {
                float* cp;
                if (LAYER1) cp = g_h + (size_t)(goff + r) * NTOT + n0;
                else        cp = Cout + (size_t)g_order[goff + r] * NTOT + n0;
                #pragma unroll
                for (int nt = 0; nt < 8; nt++) {
                    int col = wn * 64 + nt * 8 + (lane & 3) * 2;
                    float v0 = acc[mt][nt][half * 2 + 0] + bp[col];
                    float v1 = acc[mt][nt][half * 2 + 1] + bp[col + 1];
                    if (LAYER1) { v0 = gelu_tanh(v0); v1 = gelu_tanh(v1); }
                    float2 v = make_float2(v0, v1);
                    *reinterpret_cast<float2*>(cp + col) = v;
                }
            }
        }
    }
}

// ---------------------------------------------------------------------------
extern "C" void kernel_launch(void* const* d_in, const int* in_sizes, int n_in,
                              void* d_out, int out_size)
{
    const float* x     = (const float*)d_in[0];
    const void*  route = d_in[1];
    const float* W1    = (const float*)d_in[2];
    const float* b1    = (const float*)d_in[3];
    const float* W2    = (const float*)d_in[4];
    const float* b2    = (const float*)d_in[5];
    float*       out   = (float*)d_out;

    cudaFuncSetAttribute(moe_gemm<DIN, DHID, true>,
                         cudaFuncAttributeMaxDynamicSharedMemorySize, SMEM_DYN);
    cudaFuncSetAttribute(moe_gemm<DHID, DOUT, false>,
                         cudaFuncAttributeMaxDynamicSharedMemorySize, SMEM_DYN);

    route_kernel<<<1, 1024>>>((const int*)route);

    {   // Layer 1: g_h = gelu(x @ W1[m] + b1[m]) grouped by expert
        dim3 grid(DHID / 128, BTOK / 128, NEXP);
        moe_gemm<DIN, DHID, true><<<grid, 256, SMEM_DYN>>>(x, W1, b1, nullptr);
    }
    {   // Layer 2: out[tok] = g_h @ W2[m] + b2[m]
        dim3 grid(DOUT / 128, BTOK / 128, NEXP);
        moe_gemm<DHID, DOUT, false><<<grid, 256, SMEM_DYN>>>(nullptr, W2, b2, out);
    }
}

// round 4
// speedup vs baseline: 2.7585x; 1.0039x over previous
#include <cuda_runtime.h>
#include <cuda_bf16.h>
#include <stdint.h>
#include <math.h>

#define NEXP 8
#define BTOK 4096
#define DIN  1024
#define DHID 4096
#define DOUT 1024

// Scratch + bucketing state (device globals; no allocations in kernel_launch)
__device__ float g_h[(size_t)BTOK * DHID];
__device__ int   g_counts[NEXP];
__device__ int   g_offsets[NEXP];
__device__ int   g_order[BTOK];

// ---------------------------------------------------------------------------
// Helpers
// ---------------------------------------------------------------------------
__device__ __forceinline__ uint32_t smem_u32(const void* p) {
    uint32_t a;
    asm("{ .reg .u64 t; cvta.to.shared.u64 t, %1; cvt.u32.u64 %0, t; }"
        : "=r"(a) : "l"(p));
    return a;
}

__device__ __forceinline__ void ldm_x4(uint32_t* r, uint32_t addr) {
    asm volatile("ldmatrix.sync.aligned.m8n8.x4.shared.b16 {%0,%1,%2,%3}, [%4];"
                 : "=r"(r[0]), "=r"(r[1]), "=r"(r[2]), "=r"(r[3]) : "r"(addr));
}
__device__ __forceinline__ void ldm_x4_t(uint32_t* r, uint32_t addr) {
    asm volatile("ldmatrix.sync.aligned.m8n8.x4.trans.shared.b16 {%0,%1,%2,%3}, [%4];"
                 : "=r"(r[0]), "=r"(r[1]), "=r"(r[2]), "=r"(r[3]) : "r"(addr));
}

__device__ __forceinline__ void mma_bf16(float* d, const uint32_t* a,
                                         uint32_t b0, uint32_t b1) {
    asm volatile(
        "mma.sync.aligned.m16n8k16.row.col.f32.bf16.bf16.f32 "
        "{%0,%1,%2,%3}, {%4,%5,%6,%7}, {%8,%9}, {%0,%1,%2,%3};"
        : "+f"(d[0]), "+f"(d[1]), "+f"(d[2]), "+f"(d[3])
        : "r"(a[0]), "r"(a[1]), "r"(a[2]), "r"(a[3]), "r"(b0), "r"(b1));
}

__device__ __forceinline__ void sts64(uint32_t addr, uint2 v) {
    asm volatile("st.shared.v2.b32 [%0], {%1, %2};"
                 :: "r"(addr), "r"(v.x), "r"(v.y) : "memory");
}

__device__ __forceinline__ float gelu_tanh(float x) {
    float x3 = x * x * x;
    return 0.5f * x * (1.0f + tanhf(0.7978845608028654f * (x + 0.044715f * x3)));
}

__device__ __forceinline__ uint32_t pack_bf2(__nv_bfloat16 a, __nv_bfloat16 b) {
    __nv_bfloat162 t(a, b);
    return *reinterpret_cast<uint32_t*>(&t);
}

__device__ __forceinline__ void split4(float4 v, uint2& hi, uint2& lo) {
    __nv_bfloat16 h0 = __float2bfloat16(v.x);
    __nv_bfloat16 h1 = __float2bfloat16(v.y);
    __nv_bfloat16 h2 = __float2bfloat16(v.z);
    __nv_bfloat16 h3 = __float2bfloat16(v.w);
    __nv_bfloat16 l0 = __float2bfloat16(v.x - __bfloat162float(h0));
    __nv_bfloat16 l1 = __float2bfloat16(v.y - __bfloat162float(h1));
    __nv_bfloat16 l2 = __float2bfloat16(v.z - __bfloat162float(h2));
    __nv_bfloat16 l3 = __float2bfloat16(v.w - __bfloat162float(h3));
    hi.x = pack_bf2(h0, h1); hi.y = pack_bf2(h2, h3);
    lo.x = pack_bf2(l0, l1); lo.y = pack_bf2(l2, l3);
}

// ---------------------------------------------------------------------------
// Single-block routing: detect route dtype, count, scan, scatter.
// ---------------------------------------------------------------------------
__global__ __launch_bounds__(1024)
void route_kernel(const int* __restrict__ r32) {
    __shared__ int s32, scnt[NEXP], soff[NEXP];
    int tid = threadIdx.x;
    if (tid == 0) s32 = 0;
    if (tid < NEXP) scnt[tid] = 0;
    __syncthreads();

    // int64 route: every odd int32 word of the first 4096 is a zero hi-half.
    int f = 0;
    for (int i = tid * 2 + 1; i < BTOK; i += 2048) f |= r32[i];
    if (f) atomicOr(&s32, 1);
    __syncthreads();
    bool is32 = (s32 != 0);

    int mym[4], myrank[4];
    #pragma unroll
    for (int j = 0; j < 4; j++) {
        int b = tid + j * 1024;
        int m = is32 ? r32[b] : (int)((const long long*)r32)[b];
        mym[j] = m;
        myrank[j] = atomicAdd(&scnt[m], 1);
    }
    __syncthreads();
    if (tid == 0) {
        int s = 0;
        for (int m = 0; m < NEXP; m++) {
            soff[m] = s; g_offsets[m] = s; g_counts[m] = scnt[m]; s += scnt[m];
        }
    }
    __syncthreads();
    #pragma unroll
    for (int j = 0; j < 4; j++)
        g_order[soff[mym[j]] + myrank[j]] = tid + j * 1024;
}

// ---------------------------------------------------------------------------
// Grouped GEMM, mma.sync m16n8k16 bf16, split hi/lo (3 passes), fp32 acc.
// CTA tile 128x128, K-chunk 32, 8 warps (4 m x 2 n), warp tile 32x64.
// Double-buffered SMEM, padded strides (conflict-free ldmatrix).
// ---------------------------------------------------------------------------
static constexpr int ASTR_B = 80;    // A row stride, bytes (40 bf16)
static constexpr int BSTR_B = 272;   // B row stride, bytes (136 bf16)
static constexpr int A_TILE = 128 * ASTR_B;            // 10240
static constexpr int B_TILE = 32 * BSTR_B;             // 8704
static constexpr int OFF_AHI = 0;
static constexpr int OFF_ALO = A_TILE;                 // 10240
static constexpr int OFF_BHI = 2 * A_TILE;             // 20480
static constexpr int OFF_BLO = 2 * A_TILE + B_TILE;    // 29184
static constexpr int STAGE   = 2 * A_TILE + 2 * B_TILE;// 37888
static constexpr int SMEM_DYN = 2 * STAGE;             // 75776

template <int K, int NTOT, bool LAYER1>
__global__ __launch_bounds__(256)
void moe_gemm(const float* __restrict__ Ax, const float* __restrict__ W,
              const float* __restrict__ bias, float* __restrict__ Cout)
{
    const int m    = blockIdx.z;
    const int cnt  = g_counts[m];
    const int row0 = blockIdx.y * 128;
    if (row0 >= cnt) return;
    const int goff = g_offsets[m];
    const int n0   = blockIdx.x * 128;
    const int tid  = threadIdx.x;
    const int wid  = tid >> 5;
    const int lane = tid & 31;
    const int wm   = wid & 3;    // warp row 0..3  (32 rows each)
    const int wn   = wid >> 2;   // warp col 0..1  (64 cols each)

    extern __shared__ char smem_raw[];
    const uint32_t sbase = smem_u32(smem_raw);

    // ---- Per-thread global load mapping ----
    // A: 128 rows x 32 floats = 1024 float4; thread handles 4.
    const float* aptr[4];
    int akoff[4];
    #pragma unroll
    for (int j = 0; j < 4; j++) {
        int idx  = tid + j * 256;
        int row  = idx >> 3;             // 0..127
        akoff[j] = (idx & 7) * 4;        // float offset in chunk (0..28)
        int grow = row0 + row;
        int gr   = (grow < cnt) ? (goff + grow) : goff;   // clamp
        if (LAYER1) aptr[j] = Ax + (size_t)g_order[gr] * K;
        else        aptr[j] = g_h + (size_t)gr * K;
    }
    // B: 32 k-rows x 128 floats = 1024 float4; thread handles 4.
    const float* Wb = W + (size_t)m * K * NTOT + n0;
    int bkrow[4], bnoff[4];
    #pragma unroll
    for (int j = 0; j < 4; j++) {
        int idx  = tid + j * 256;
        bkrow[j] = idx >> 5;             // 0..31
        bnoff[j] = (idx & 31) * 4;       // 0..124
    }

    // SMEM store addresses (stage-relative, bytes)
    uint32_t a_sts[4], b_sts[4];
    #pragma unroll
    for (int j = 0; j < 4; j++) {
        int idx = tid + j * 256;
        a_sts[j] = (uint32_t)((idx >> 3) * ASTR_B + (idx & 7) * 8);
        b_sts[j] = (uint32_t)((idx >> 5) * BSTR_B + (idx & 31) * 8);
    }

    // ldmatrix base addresses (stage-relative)
    // A frag (m16k16): row = wm*32 + mt*16 + (lane&15); koff = (lane>>4)*8 elems
    const uint32_t a_ldm = (uint32_t)((wm * 32 + (lane & 15)) * ASTR_B + (lane >> 4) * 16);
    // B frag (k16n16, trans): krow = kstep*16 + (lane&15); col = wn*64 + ng*16 + (lane>>4)*8
    const uint32_t b_ldm = (uint32_t)((lane & 15) * BSTR_B + (wn * 64 + (lane >> 4) * 8) * 2);

    float acc[2][8][4] = {};

    const int NC = K / 32;
    float4 av[4], bv[4];

    // Prefetch chunk 0
    #pragma unroll
    for (int j = 0; j < 4; j++)
        av[j] = *reinterpret_cast<const float4*>(aptr[j] + akoff[j]);
    #pragma unroll
    for (int j = 0; j < 4; j++)
        bv[j] = *reinterpret_cast<const float4*>(Wb + (size_t)bkrow[j] * NTOT + bnoff[j]);

    // Store chunk 0 into stage 0
    {
        const uint32_t st = sbase;
        #pragma unroll
        for (int j = 0; j < 4; j++) {
            uint2 hi, lo; split4(av[j], hi, lo);
            sts64(st + OFF_AHI + a_sts[j], hi);
            sts64(st + OFF_ALO + a_sts[j], lo);
        }
        #pragma unroll
        for (int j = 0; j < 4; j++) {
            uint2 hi, lo; split4(bv[j], hi, lo);
            sts64(st + OFF_BHI + b_sts[j], hi);
            sts64(st + OFF_BLO + b_sts[j], lo);
        }
    }
    __syncthreads();

    for (int c = 0; c < NC; c++) {
        // Prefetch next chunk into registers (overlaps with MMA below)
        if (c + 1 < NC) {
            const int k0 = (c + 1) * 32;
            #pragma unroll
            for (int j = 0; j < 4; j++)
                av[j] = *reinterpret_cast<const float4*>(aptr[j] + k0 + akoff[j]);
            #pragma unroll
            for (int j = 0; j < 4; j++)
                bv[j] = *reinterpret_cast<const float4*>(
                            Wb + (size_t)(k0 + bkrow[j]) * NTOT + bnoff[j]);
        }

        // MMA on current stage
        const uint32_t st = sbase + (c & 1) * STAGE;
        #pragma unroll
        for (int ks = 0; ks < 2; ks++) {
            uint32_t ahi[2][4], alo[2][4];
            #pragma unroll
            for (int mt = 0; mt < 2; mt++) {
                uint32_t aoff = a_ldm + mt * 16 * ASTR_B + ks * 32;
                ldm_x4(ahi[mt], st + OFF_AHI + aoff);
                ldm_x4(alo[mt], st + OFF_ALO + aoff);
            }
            #pragma unroll
            for (int ng = 0; ng < 4; ng++) {
                uint32_t bhi[4], blo[4];
                uint32_t boff = b_ldm + ks * 16 * BSTR_B + ng * 32;
                ldm_x4_t(bhi, st + OFF_BHI + boff);
                ldm_x4_t(blo, st + OFF_BLO + boff);
                #pragma unroll
                for (int mt = 0; mt < 2; mt++) {
                    float* d0 = acc[mt][ng * 2 + 0];
                    float* d1 = acc[mt][ng * 2 + 1];
                    mma_bf16(d0, ahi[mt], bhi[0], bhi[1]);
                    mma_bf16(d1, ahi[mt], bhi[2], bhi[3]);
                    mma_bf16(d0, ahi[mt], blo[0], blo[1]);
                    mma_bf16(d1, ahi[mt], blo[2], blo[3]);
                    mma_bf16(d0, alo[mt], bhi[0], bhi[1]);
                    mma_bf16(d1, alo[mt], bhi[2], bhi[3]);
                }
            }
        }

        // Store prefetched chunk into the other stage
        if (c + 1 < NC) {
            const uint32_t st2 = sbase + ((c + 1) & 1) * STAGE;
            #pragma unroll
            for (int j = 0; j < 4; j++) {
                uint2 hi, lo; split4(av[j], hi, lo);
                sts64(st2 + OFF_AHI + a_sts[j], hi);
                sts64(st2 + OFF_ALO + a_sts[j], lo);
            }
            #pragma unroll
            for (int j = 0; j < 4; j++) {
                uint2 hi, lo; split4(bv[j], hi, lo);
                sts64(st2 + OFF_BHI + b_sts[j], hi);
                sts64(st2 + OFF_BLO + b_sts[j], lo);
            }
        }
        __syncthreads();
    }

    // ---- Epilogue ----
    // D frag m16n8: d0,d1 -> row lane>>2, cols (lane&3)*2+{0,1}; d2,d3 -> row+8
    const float* bp = bias + (size_t)m * NTOT + n0;
    #pragma unroll
    for (int mt = 0; mt < 2; mt++) {
        #pragma unroll
        for (int half = 0; half < 2; half++) {
            int rloc = wm * 32 + mt * 16 + (lane >> 2) + half * 8;
            int r    = row0 + rloc;
            if (r < cnt) {
                float* cp;
                if (LAYER1) cp = g_h + (size_t)(goff + r) * NTOT + n0;
                else        cp = Cout + (size_t)g_order[goff + r] * NTOT + n0;
                #pragma unroll
                for (int nt = 0; nt < 8; nt++) {
                    int col = wn * 64 + nt * 8 + (lane & 3) * 2;
                    float v0 = acc[mt][nt][half * 2 + 0] + bp[col];
                    float v1 = acc[mt][nt][half * 2 + 1] + bp[col + 1];
                    if (LAYER1) { v0 = gelu_tanh(v0); v1 = gelu_tanh(v1); }
                    float2 v = make_float2(v0, v1);
                    *reinterpret_cast<float2*>(cp + col) = v;
                }
            }
        }
    }
}

// ---------------------------------------------------------------------------
extern "C" void kernel_launch(void* const* d_in, const int* in_sizes, int n_in,
                              void* d_out, int out_size)
{
    const float* x     = (const float*)d_in[0];
    const void*  route = d_in[1];
    const float* W1    = (const float*)d_in[2];
    const float* b1    = (const float*)d_in[3];
    const float* W2    = (const float*)d_in[4];
    const float* b2    = (const float*)d_in[5];
    float*       out   = (float*)d_out;

    cudaFuncSetAttribute(moe_gemm<DIN, DHID, true>,
                         cudaFuncAttributeMaxDynamicSharedMemorySize, SMEM_DYN);
    cudaFuncSetAttribute(moe_gemm<DHID, DOUT, false>,
                         cudaFuncAttributeMaxDynamicSharedMemorySize, SMEM_DYN);

    route_kernel<<<1, 1024>>>((const int*)route);

    {   // Layer 1: g_h = gelu(x @ W1[m] + b1[m]) grouped by expert
        dim3 grid(DHID / 128, BTOK / 128, NEXP);
        moe_gemm<DIN, DHID, true><<<grid, 256, SMEM_DYN>>>(x, W1, b1, nullptr);
    }
    {   // Layer 2: out[tok] = g_h @ W2[m] + b2[m]
        dim3 grid(DOUT / 128, BTOK / 128, NEXP);
        moe_gemm<DHID, DOUT, false><<<grid, 256, SMEM_DYN>>>(nullptr, W2, b2, out);
    }
}